// round 14
// baseline (speedup 1.0000x reference)
#include <cuda_runtime.h>
#include <cuda_bf16.h>
#include <cstdint>
#include <cstddef>

#define EPSR 0.001f
#define BB 32768

__device__ float g_gam[2];

constexpr size_t F128 = 128*128;
constexpr size_t OFF_H   = 0;
constexpr size_t OFF_EPS = OFF_H + 768*768;
constexpr size_t OFF_CXW = OFF_EPS + (size_t)BB*256;
constexpr size_t OFF_MT  = OFF_CXW + (size_t)BB*256;
constexpr size_t OFF_AP  = OFF_MT  + F128;
constexpr size_t OFF_AM  = OFF_AP  + F128;
constexpr size_t OFF_AI  = OFF_AM  + F128;
constexpr size_t OFF_G   = OFF_AI  + F128;
constexpr size_t OFF_GI  = OFF_G   + F128;
constexpr size_t OFF_MM  = OFF_GI  + F128;
constexpr size_t OFF_E11 = OFF_MM  + F128;
constexpr size_t OFF_S   = OFF_E11 + F128;
constexpr size_t OFF_SI  = OFF_S   + F128;
constexpr size_t OFF_T2  = OFF_SI  + F128;
constexpr size_t OFF_T3  = OFF_T2  + F128;
constexpr size_t OFF_VR  = OFF_T3  + F128;
constexpr size_t OFF_T1  = OFF_VR  + 768*128;
constexpr size_t OFF_E   = OFF_T1  + 768*128;
constexpr size_t OFF_EI  = OFF_E   + 256*256;
constexpr size_t OFF_WFM = OFF_EI  + 256*256;
constexpr size_t OFF_WB1 = OFF_WFM + 256*256;
constexpr size_t OFF_DNT = OFF_WB1 + 256*256;
constexpr size_t OFF_WB2 = OFF_DNT + 256*256;
constexpr size_t OFF_IL  = OFF_WB2 + 256*128;
constexpr size_t SCR_TOT = OFF_IL  + 256;

__device__ float g_scr[SCR_TOT];

// bf16 split weight buffers
__device__ __nv_bfloat16 g_wh1[256*384];
__device__ __nv_bfloat16 g_wl1[256*384];
__device__ __nv_bfloat16 g_wh2[384*640];
__device__ __nv_bfloat16 g_wl2[384*640];

// ---------- packed fp32x2 helpers ----------
__device__ __forceinline__ unsigned long long pk2(float x, float y) {
    unsigned long long r;
    asm("mov.b64 %0, {%1,%2};" : "=l"(r) : "f"(x), "f"(y));
    return r;
}
__device__ __forceinline__ void upk2(unsigned long long v, float &x, float &y) {
    asm("mov.b64 {%0,%1}, %2;" : "=f"(x), "=f"(y) : "l"(v));
}
__device__ __forceinline__ void ffma2(unsigned long long &d, unsigned long long a,
                                      unsigned long long b) {
    asm("fma.rn.f32x2 %0, %1, %2, %0;" : "+l"(d) : "l"(a), "l"(b));
}

__device__ __forceinline__ uint32_t s2u(const void* p) {
    uint32_t a;
    asm("{ .reg .u64 t; cvta.to.shared.u64 t, %1; cvt.u32.u64 %0, t; }"
        : "=r"(a) : "l"(p));
    return a;
}
__device__ __forceinline__ void ldm4(uint32_t* r, uint32_t addr) {
    asm volatile("ldmatrix.sync.aligned.m8n8.x4.shared.b16 {%0,%1,%2,%3}, [%4];"
        : "=r"(r[0]), "=r"(r[1]), "=r"(r[2]), "=r"(r[3]) : "r"(addr));
}
#define MMA16816(d, a, b) \
    asm volatile("mma.sync.aligned.m16n8k16.row.col.f32.bf16.bf16.f32 " \
        "{%0,%1,%2,%3}, {%4,%5,%6,%7}, {%8,%9}, {%0,%1,%2,%3};" \
        : "+f"((d)[0]), "+f"((d)[1]), "+f"((d)[2]), "+f"((d)[3]) \
        : "r"((a)[0]), "r"((a)[1]), "r"((a)[2]), "r"((a)[3]), \
          "r"((b)[0]), "r"((b)[1]))

// ---------- tensor-core batch GEMM with split-bf16 (3 products) ----------
__global__ __launch_bounds__(256) void mmagemm(
    const float* __restrict__ A0, int k0,
    const float* __restrict__ A1, int k1,
    const float* __restrict__ A2, int k2,
    const __nv_bfloat16* __restrict__ Wh, const __nv_bfloat16* __restrict__ Wl,
    int ktot, int Ntot, int n0,
    float* __restrict__ C0, int ldc0, float* __restrict__ C1, int ldc1)
{
    __shared__ __nv_bfloat16 sAh[128][40];
    __shared__ __nv_bfloat16 sAl[128][40];
    __shared__ __nv_bfloat16 sWh[128][40];
    __shared__ __nv_bfloat16 sWl[128][40];

    int tid = threadIdx.x;
    int bm = blockIdx.y << 7, bn = blockIdx.x << 7;
    int wi = tid >> 5, lane = tid & 31;
    int wm = (wi & 3) << 5;
    int wn = (wi >> 2) << 6;

    float acc[2][8][4];
#pragma unroll
    for (int mf = 0; mf < 2; mf++)
#pragma unroll
        for (int nf = 0; nf < 8; nf++)
#pragma unroll
            for (int i = 0; i < 4; i++) acc[mf][nf][i] = 0.f;

    int am = tid >> 1, ah = tid & 1;
    float4 pa[4];
    uint4 pwh[2], pwl[2];

    auto ldA = [&](int off) {
        const float* As; int so, sk;
        if (off < k0)           { As = A0; so = off;           sk = k0; }
        else if (off < k0 + k1) { As = A1; so = off - k0;      sk = k1; }
        else                    { As = A2; so = off - k0 - k1; sk = k2; }
        const float4* p = (const float4*)(As + (size_t)(bm + am) * sk + so + ah * 16);
        pa[0] = p[0]; pa[1] = p[1]; pa[2] = p[2]; pa[3] = p[3];
    };
    auto ldW = [&](int off) {
        const uint4* ph = (const uint4*)(Wh + (size_t)(bn + am) * ktot + off + ah * 16);
        pwh[0] = ph[0]; pwh[1] = ph[1];
        const uint4* pl = (const uint4*)(Wl + (size_t)(bn + am) * ktot + off + ah * 16);
        pwl[0] = pl[0]; pwl[1] = pl[1];
    };
    auto stAW = [&]() {
        const float* pf = (const float*)pa;
        uint32_t hh[8], ll[8];
#pragma unroll
        for (int i = 0; i < 8; i++) {
            float x = pf[2 * i], y = pf[2 * i + 1];
            __nv_bfloat162 hb = __float22bfloat162_rn(make_float2(x, y));
            float2 hf = __bfloat1622float2(hb);
            __nv_bfloat162 lb = __float22bfloat162_rn(make_float2(x - hf.x, y - hf.y));
            hh[i] = *(uint32_t*)&hb; ll[i] = *(uint32_t*)&lb;
        }
        int co = ah << 4;
        *(uint4*)&sAh[am][co]     = make_uint4(hh[0], hh[1], hh[2], hh[3]);
        *(uint4*)&sAh[am][co + 8] = make_uint4(hh[4], hh[5], hh[6], hh[7]);
        *(uint4*)&sAl[am][co]     = make_uint4(ll[0], ll[1], ll[2], ll[3]);
        *(uint4*)&sAl[am][co + 8] = make_uint4(ll[4], ll[5], ll[6], ll[7]);
        *(uint4*)&sWh[am][co]     = pwh[0];
        *(uint4*)&sWh[am][co + 8] = pwh[1];
        *(uint4*)&sWl[am][co]     = pwl[0];
        *(uint4*)&sWl[am][co + 8] = pwl[1];
    };

    ldA(0); ldW(0); stAW();
    __syncthreads();

    int ar = lane & 15, akq = (lane >> 4) << 3;
    int brn = lane & 7, bgrp = lane >> 3;
    int bro = (bgrp >> 1) << 3, bko = (bgrp & 1) << 3;

    int nch = ktot >> 5;
    for (int c = 0; c < nch; c++) {
        bool more = (c + 1) < nch;
        if (more) { ldA((c + 1) << 5); ldW((c + 1) << 5); }
#pragma unroll
        for (int ks = 0; ks < 2; ks++) {
            int kc = ks << 4;
            uint32_t ahf[2][4], alf[2][4], bf[8][2];
            ldm4(ahf[0], s2u(&sAh[wm + ar][kc + akq]));
            ldm4(ahf[1], s2u(&sAh[wm + 16 + ar][kc + akq]));
#pragma unroll
            for (int q = 0; q < 4; q++) {
                uint32_t r4[4];
                ldm4(r4, s2u(&sWh[wn + (q << 4) + bro + brn][kc + bko]));
                bf[2 * q][0] = r4[0]; bf[2 * q][1] = r4[1];
                bf[2 * q + 1][0] = r4[2]; bf[2 * q + 1][1] = r4[3];
            }
#pragma unroll
            for (int mf = 0; mf < 2; mf++)
#pragma unroll
                for (int nf = 0; nf < 8; nf++)
                    MMA16816(acc[mf][nf], ahf[mf], bf[nf]);
            ldm4(alf[0], s2u(&sAl[wm + ar][kc + akq]));
            ldm4(alf[1], s2u(&sAl[wm + 16 + ar][kc + akq]));
#pragma unroll
            for (int mf = 0; mf < 2; mf++)
#pragma unroll
                for (int nf = 0; nf < 8; nf++)
                    MMA16816(acc[mf][nf], alf[mf], bf[nf]);
#pragma unroll
            for (int q = 0; q < 4; q++) {
                uint32_t r4[4];
                ldm4(r4, s2u(&sWl[wn + (q << 4) + bro + brn][kc + bko]));
                bf[2 * q][0] = r4[0]; bf[2 * q][1] = r4[1];
                bf[2 * q + 1][0] = r4[2]; bf[2 * q + 1][1] = r4[3];
            }
#pragma unroll
            for (int mf = 0; mf < 2; mf++)
#pragma unroll
                for (int nf = 0; nf < 8; nf++)
                    MMA16816(acc[mf][nf], ahf[mf], bf[nf]);
        }
        __syncthreads();
        if (more) { stAW(); __syncthreads(); }
    }

    int tm = lane >> 2, tn = (lane & 3) << 1;
#pragma unroll
    for (int mf = 0; mf < 2; mf++)
#pragma unroll
        for (int nf = 0; nf < 8; nf++) {
            int m = bm + wm + (mf << 4) + tm;
            int n = bn + wn + (nf << 3) + tn;
            float* d0; float* d1;
            if (n < n0) {
                d0 = C0 + (size_t)m * ldc0 + n;
                d1 = C0 + (size_t)(m + 8) * ldc0 + n;
            } else {
                d0 = C1 + (size_t)m * ldc1 + (n - n0);
                d1 = C1 + (size_t)(m + 8) * ldc1 + (n - n0);
            }
            *(float2*)d0 = make_float2(acc[mf][nf][0], acc[mf][nf][1]);
            *(float2*)d1 = make_float2(acc[mf][nf][2], acc[mf][nf][3]);
        }
}

// ---------- weight split-conversion kernels ----------
__global__ void k_cvtW1(__nv_bfloat16* Wh, __nv_bfloat16* Wl,
                        const float* H, const float* D12) {
    int t = blockIdx.x * blockDim.x + threadIdx.x;
    if (t >= 256 * 384) return;
    int n = t / 384, k = t - n * 384;
    float v = (k < 256) ? -H[(size_t)(256 + n) * 768 + k] : D12[n * 128 + (k - 256)];
    __nv_bfloat16 h = __float2bfloat16(v);
    Wh[t] = h;
    Wl[t] = __float2bfloat16(v - __bfloat162float(h));
}
__global__ void k_cvtW2(__nv_bfloat16* Wh, __nv_bfloat16* Wl,
                        const float* WFM, const float* WB1, const float* WB2,
                        const float* C2, const float* D21, const float* MT) {
    int t = blockIdx.x * blockDim.x + threadIdx.x;
    if (t >= 384 * 640) return;
    int n = t / 640, k = t - n * 640;
    float v;
    if (n < 256) {
        v = (k < 256) ? WFM[n * 256 + k]
          : (k < 512) ? WB1[n * 256 + (k - 256)]
                      : WB2[n * 128 + (k - 512)];
    } else {
        int m = n - 256;
        v = (k < 256) ? C2[m * 256 + k]
          : (k < 512) ? D21[m * 256 + (k - 256)]
                      : g_gam[0] * MT[m * 128 + (k - 512)];
    }
    __nv_bfloat16 h = __float2bfloat16(v);
    Wh[t] = h;
    Wl[t] = __float2bfloat16(v - __bfloat162float(h));
}

// ---------- SIMT GEMM (phase A only) ----------
__global__ __launch_bounds__(256) void gemm(
    float* __restrict__ C, int ldc,
    const float* __restrict__ A, int lda, int tA,
    const float* __restrict__ Bm, int ldb, int tB,
    int K, float alpha, float beta, int amode)
{
    __shared__ float sA[16][132];
    __shared__ float sB[16][132];
    int tid = threadIdx.x;
    int bm = blockIdx.y << 7, bn = blockIdx.x << 7;
    int ty = tid >> 4, tx = tid & 15;
    float4 rA[2], rB[2];

    auto ldAa = [&](int k0) {
#pragma unroll
        for (int p = 0; p < 2; p++) {
            int idx = tid + (p << 8);
            if (!tA) {
                int r = idx >> 2, c4 = (idx & 3) << 2;
                rA[p] = *(const float4*)(A + (size_t)(bm + r) * lda + k0 + c4);
            } else {
                int kk = idx >> 5, m4 = (idx & 31) << 2;
                rA[p] = *(const float4*)(A + (size_t)(k0 + kk) * lda + bm + m4);
            }
        }
    };
    auto stAa = [&]() {
#pragma unroll
        for (int p = 0; p < 2; p++) {
            int idx = tid + (p << 8);
            if (!tA) {
                int r = idx >> 2, c4 = (idx & 3) << 2;
                sA[c4][r] = rA[p].x; sA[c4 + 1][r] = rA[p].y;
                sA[c4 + 2][r] = rA[p].z; sA[c4 + 3][r] = rA[p].w;
            } else {
                int kk = idx >> 5, m4 = (idx & 31) << 2;
                *(float4*)&sA[kk][m4] = rA[p];
            }
        }
    };
    auto ldBb = [&](int k0) {
#pragma unroll
        for (int p = 0; p < 2; p++) {
            int idx = tid + (p << 8);
            if (!tB) {
                int kk = idx >> 5, n4 = (idx & 31) << 2;
                rB[p] = *(const float4*)(Bm + (size_t)(k0 + kk) * ldb + bn + n4);
            } else {
                int n = idx >> 2, c4 = (idx & 3) << 2;
                rB[p] = *(const float4*)(Bm + (size_t)(bn + n) * ldb + k0 + c4);
            }
        }
    };
    auto stBb = [&]() {
#pragma unroll
        for (int p = 0; p < 2; p++) {
            int idx = tid + (p << 8);
            if (!tB) {
                int kk = idx >> 5, n4 = (idx & 31) << 2;
                *(float4*)&sB[kk][n4] = rB[p];
            } else {
                int n = idx >> 2, c4 = (idx & 3) << 2;
                sB[c4][n] = rB[p].x; sB[c4 + 1][n] = rB[p].y;
                sB[c4 + 2][n] = rB[p].z; sB[c4 + 3][n] = rB[p].w;
            }
        }
    };

    unsigned long long acc[8][4];
#pragma unroll
    for (int r = 0; r < 8; r++)
#pragma unroll
        for (int c = 0; c < 4; c++) acc[r][c] = 0ull;

    ldAa(0); ldBb(0); stAa(); stBb();
    __syncthreads();

    for (int k0 = 0; k0 < K; k0 += 16) {
        bool more = (k0 + 16) < K;
        if (more) { ldAa(k0 + 16); ldBb(k0 + 16); }
#pragma unroll
        for (int kk = 0; kk < 16; kk++) {
            float4 a0 = *(float4*)&sA[kk][ty << 3];
            float4 a1 = *(float4*)&sA[kk][(ty << 3) + 4];
            float4 b0 = *(float4*)&sB[kk][tx << 3];
            float4 b1 = *(float4*)&sB[kk][(tx << 3) + 4];
            unsigned long long bp0 = pk2(b0.x, b0.y), bp1 = pk2(b0.z, b0.w);
            unsigned long long bp2 = pk2(b1.x, b1.y), bp3 = pk2(b1.z, b1.w);
            float ar[8] = {a0.x, a0.y, a0.z, a0.w, a1.x, a1.y, a1.z, a1.w};
#pragma unroll
            for (int r = 0; r < 8; r++) {
                unsigned long long ap = pk2(ar[r], ar[r]);
                ffma2(acc[r][0], ap, bp0);
                ffma2(acc[r][1], ap, bp1);
                ffma2(acc[r][2], ap, bp2);
                ffma2(acc[r][3], ap, bp3);
            }
        }
        __syncthreads();
        if (more) { stAa(); stBb(); __syncthreads(); }
    }

    float al = alpha;
    if (amode == 1) al *= g_gam[0];
    else if (amode == 2) al *= g_gam[1];
#pragma unroll
    for (int r = 0; r < 8; r++) {
        float* crow = C + (size_t)(bm + (ty << 3) + r) * ldc + bn + (tx << 3);
        float o[8];
#pragma unroll
        for (int c = 0; c < 4; c++) upk2(acc[r][c], o[2 * c], o[2 * c + 1]);
        if (beta != 0.f) {
            float4 c0 = *(float4*)crow, c1 = *(float4*)(crow + 4);
            o[0] = al * o[0] + beta * c0.x; o[1] = al * o[1] + beta * c0.y;
            o[2] = al * o[2] + beta * c0.z; o[3] = al * o[3] + beta * c0.w;
            o[4] = al * o[4] + beta * c1.x; o[5] = al * o[5] + beta * c1.y;
            o[6] = al * o[6] + beta * c1.z; o[7] = al * o[7] + beta * c1.w;
        } else {
#pragma unroll
            for (int i = 0; i < 8; i++) o[i] *= al;
        }
        *(float4*)crow = make_float4(o[0], o[1], o[2], o[3]);
        *(float4*)(crow + 4) = make_float4(o[4], o[5], o[6], o[7]);
    }
}

// ---------- register-resident Gauss-Jordan inverse, n=128 ----------
__global__ __launch_bounds__(1024) void gj(float* dst, const float* src, int ld) {
    __shared__ float colb[2][128];
    __shared__ float rowb[2][128];
    int t = threadIdx.x;
    int j = t & 127, q = t >> 7;
    int base = q << 4;
    float v[16];
#pragma unroll
    for (int i = 0; i < 16; i++) v[i] = src[(size_t)(base + i) * ld + j];
    if (j == 0) {
#pragma unroll
        for (int i = 0; i < 16; i++) colb[0][base + i] = v[i];
    }
    if (q == 0) rowb[0][j] = v[0];
    __syncthreads();
    for (int k = 0; k < 128; k++) {
        int pb = k & 1, nb = pb ^ 1;
        float rk  = rowb[pb][j];
        float piv = rowb[pb][k];
        float iv  = 1.f / piv;
        float a   = rk * iv;
        bool jk = (j == k);
#pragma unroll
        for (int i = 0; i < 16; i++) {
            int gi = base + i;
            float c = colb[pb][gi];
            float nv = v[i] - c * a;
            if (gi == k) nv = a;
            if (jk) nv = (gi == k) ? iv : -c * iv;
            v[i] = nv;
        }
        if (k < 127) {
            int kn = k + 1;
            if (j == kn) {
#pragma unroll
                for (int i = 0; i < 16; i++) colb[nb][base + i] = v[i];
            }
            if ((kn >> 4) == q) rowb[nb][j] = v[kn & 15];
        }
        __syncthreads();
    }
#pragma unroll
    for (int i = 0; i < 16; i++) dst[(size_t)(base + i) * 128 + j] = v[i];
}

// ---------- small elementwise helpers ----------
__global__ void k_scal(const float* sg) {
    float g = sg[0] * sg[0];
    g_gam[0] = g; g_gam[1] = 1.f / g;
}
__global__ void k_mmpost(const float* Mm, const float* Y3, float* Ap, float* Am) {
    int t = blockIdx.x * blockDim.x + threadIdx.x;
    int i = t >> 7, j = t & 127;
    float v = Mm[t] + Y3[t] - Y3[j * 128 + i] + ((i == j) ? EPSR : 0.f);
    float d = (i == j) ? 1.f : 0.f;
    Ap[t] = d + v; Am[t] = d - v;
}
__global__ void k_addeye(float* A, int ld, int n, float v) {
    int t = blockIdx.x * blockDim.x + threadIdx.x;
    if (t < n) A[(size_t)t * ld + t] += v;
}
__global__ void k_axcopy(float* dst, int ldd, const float* src, int lds,
                         int rows, int cols, float al, float be) {
    int t = blockIdx.x * blockDim.x + threadIdx.x;
    if (t >= rows * cols) return;
    int i = t / cols, j = t - i * cols;
    float v = al * src[(size_t)i * lds + j];
    if (be != 0.f) v += be * dst[(size_t)i * ldd + j];
    dst[(size_t)i * ldd + j] = v;
}
__global__ void k_buildE(float* E, const float* H, const float* Y) {
    int t = blockIdx.x * blockDim.x + threadIdx.x;
    int i = t >> 8, j = t & 255;
    E[t] = 0.5f * (H[(size_t)i * 768 + j] + H[(size_t)(512 + i) * 768 + 512 + j]
                   + Y[t] - Y[(size_t)j * 256 + i]);
}
__global__ void k_buildrec(float* DnT, float* IL, const float* H) {
    const float* hh = H + 256 * 768 + 256;
    int t = blockIdx.x * blockDim.x + threadIdx.x;
    int i = t >> 8, j = t & 255;
    DnT[t] = (j > i) ? -hh[(size_t)j * 768 + i] : 0.f;
    if (t < 256) IL[t] = 1.f / hh[(size_t)t * 768 + t];
}

// ---------- register-resident tanh recurrence ----------
// CTA = 64 batch rows, 256 threads. Thread (r = tid>>3, ln = tid&7) keeps
// rows {r, r+32} x columns {ln, ln+8, ..., ln+248} in registers.
// DnT row i staged once per iteration into double-buffered smem.
__global__ __launch_bounds__(256) void recur(const float* __restrict__ cxw,
                                             float* __restrict__ eps,
                                             const float* __restrict__ DnT,
                                             const float* __restrict__ IL) {
    __shared__ float sd[2][256];
    __shared__ float se[64];
    __shared__ float sil[256];
    int tid = threadIdx.x;
    int r = tid >> 3, ln = tid & 7;
    int b0 = blockIdx.x << 6;
    size_t row0 = (size_t)(b0 + r) * 256;
    size_t row1 = (size_t)(b0 + r + 32) * 256;

    float a0[32], a1[32];
#pragma unroll
    for (int c = 0; c < 32; c++) {
        a0[c] = cxw[row0 + (c << 3) + ln];
        a1[c] = cxw[row1 + (c << 3) + ln];
    }
    sil[tid] = IL[tid];
    sd[0][tid] = DnT[tid];
    float nv0 = a0[0], nv1 = a1[0];   // pivot value for column 0 (owner ln==0)
    float eo0 = 0.f, eo1 = 0.f;
    __syncthreads();

    for (int i = 0; i < 256; i++) {
        if (ln == (i & 7)) {
            float il = sil[i];
            eo0 = tanhf(nv0 * il);
            eo1 = tanhf(nv1 * il);
            se[r] = eo0; se[r + 32] = eo1;
        }
        __syncthreads();
        float e0 = se[r], e1 = se[r + 32];
        const float* d = sd[i & 1];
        if (tid < 256 && i < 255) sd[(i + 1) & 1][tid] = DnT[((i + 1) << 8) + tid];
#pragma unroll
        for (int c = 0; c < 32; c++) {
            int dji = ((c << 3) + ln) - i;
            float dv = d[(c << 3) + ln];
            if (dji > 0) {
                a0[c] = fmaf(e0, dv, a0[c]);
                a1[c] = fmaf(e1, dv, a1[c]);
            }
            if (dji == 0) { a0[c] = eo0; a1[c] = eo1; }
            if (dji == 1) { nv0 = a0[c]; nv1 = a1[c]; }
        }
        __syncthreads();
    }
#pragma unroll
    for (int c = 0; c < 32; c++) {
        eps[row0 + (c << 3) + ln] = a0[c];
        eps[row1 + (c << 3) + ln] = a1[c];
    }
}

static inline void GEMM(float* C, int ldc, const float* A, int lda, int tA,
                        const float* B, int ldb, int tB,
                        int M, int N, int K, float al, float be, int am) {
    dim3 g(N >> 7, M >> 7);
    gemm<<<g, 256>>>(C, ldc, A, lda, tA, B, ldb, tB, K, al, be, am);
}

extern "C" void kernel_launch(void* const* d_in, const int* in_sizes, int n_in,
                              void* d_out, int out_size) {
    const float* w   = (const float*)d_in[0];
    const float* xi  = (const float*)d_in[1];
    const float* X   = (const float*)d_in[2];
    const float* Y   = (const float*)d_in[3];
    const float* B2  = (const float*)d_in[4];
    const float* C2  = (const float*)d_in[5];
    const float* D21 = (const float*)d_in[6];
    const float* X3  = (const float*)d_in[7];
    const float* Y3  = (const float*)d_in[8];
    const float* sg  = (const float*)d_in[9];
    const float* D12 = (const float*)d_in[10];

    float* S0 = nullptr;
    cudaGetSymbolAddress((void**)&S0, g_scr);
    __nv_bfloat16 *WH1, *WL1, *WH2, *WL2;
    cudaGetSymbolAddress((void**)&WH1, g_wh1);
    cudaGetSymbolAddress((void**)&WL1, g_wl1);
    cudaGetSymbolAddress((void**)&WH2, g_wh2);
    cudaGetSymbolAddress((void**)&WL2, g_wl2);

    float *H = S0 + OFF_H, *EPS = S0 + OFF_EPS, *CXW = S0 + OFF_CXW, *MT = S0 + OFF_MT,
          *AP = S0 + OFF_AP, *AM = S0 + OFF_AM, *AI = S0 + OFF_AI, *G = S0 + OFF_G,
          *GI = S0 + OFF_GI, *MM = S0 + OFF_MM, *E11 = S0 + OFF_E11, *Sm = S0 + OFF_S,
          *SIi = S0 + OFF_SI, *T2 = S0 + OFF_T2, *T3 = S0 + OFF_T3, *VR = S0 + OFF_VR,
          *T1 = S0 + OFF_T1, *E = S0 + OFF_E, *EI = S0 + OFF_EI, *WFM = S0 + OFF_WFM,
          *WB1 = S0 + OFF_WB1, *DNT = S0 + OFF_DNT, *WB2 = S0 + OFF_WB2, *IL = S0 + OFF_IL;

    float* u  = (float*)d_out;
    float* xn = (float*)d_out + (size_t)BB * 128;

    k_scal<<<1, 1>>>(sg);
    // Cayley: Mt = (I - Mm) inv(I + Mm)
    GEMM(MM, 128, X3, 128, 0, X3, 128, 1, 128, 128, 128, 1.f, 0.f, 0);
    k_mmpost<<<64, 256>>>(MM, Y3, AP, AM);
    gj<<<1, 1024>>>(AI, AP, 128);
    GEMM(MT, 128, AM, 128, 0, AI, 128, 0, 128, 128, 128, 1.f, 0.f, 0);
    // G = I - Mt^T Mt ; Ginv
    GEMM(G, 128, MT, 128, 1, MT, 128, 0, 128, 128, 128, -1.f, 0.f, 0);
    k_addeye<<<1, 128>>>(G, 128, 128, 1.f);
    gj<<<1, 1024>>>(GI, G, 128);
    // vec_R = [-C2^T Mt ; -D21^T Mt - D12 ; B2]
    GEMM(VR, 128, C2, 256, 1, MT, 128, 0, 256, 128, 128, -1.f, 0.f, 0);
    k_axcopy<<<128, 256>>>(VR + 256 * 128, 128, D12, 128, 256, 128, -1.f, 0.f);
    GEMM(VR + 256 * 128, 128, D21, 256, 1, MT, 128, 0, 256, 128, 128, -1.f, 1.f, 0);
    k_axcopy<<<128, 256>>>(VR + 512 * 128, 128, B2, 128, 256, 128, 1.f, 0.f);
    // H = X^T X + eps I + (1/g) VR Ginv VR^T + (1/g) VQ VQ^T
    GEMM(H, 768, X, 768, 1, X, 768, 0, 768, 768, 768, 1.f, 0.f, 0);
    k_addeye<<<3, 256>>>(H, 768, 768, EPSR);
    GEMM(T1, 128, VR, 128, 0, GI, 128, 0, 768, 128, 128, 1.f, 0.f, 0);
    GEMM(H, 768, T1, 128, 0, VR, 128, 1, 768, 768, 128, 1.f, 1.f, 2);
    GEMM(H, 768, C2, 256, 1, C2, 256, 0, 256, 256, 128, 1.f, 1.f, 2);
    GEMM(H + 256, 768, C2, 256, 1, D21, 256, 0, 256, 256, 128, 1.f, 1.f, 2);
    GEMM(H + 256 * 768, 768, D21, 256, 1, C2, 256, 0, 256, 256, 128, 1.f, 1.f, 2);
    GEMM(H + 256 * 768 + 256, 768, D21, 256, 1, D21, 256, 0, 256, 256, 128, 1.f, 1.f, 2);
    k_buildE<<<256, 256>>>(E, H, Y);
    k_buildrec<<<256, 256>>>(DNT, IL, H);
    k_cvtW1<<<384, 256>>>(WH1, WL1, H, D12);
    // inv(E) via 2x2 block Schur
    gj<<<1, 1024>>>(E11, E, 256);
    GEMM(T2, 128, E + 128 * 256, 256, 0, E11, 128, 0, 128, 128, 128, 1.f, 0.f, 0);
    k_axcopy<<<64, 256>>>(Sm, 128, E + 128 * 256 + 128, 256, 128, 128, 1.f, 0.f);
    GEMM(Sm, 128, T2, 128, 0, E + 128, 256, 0, 128, 128, 128, -1.f, 1.f, 0);
    gj<<<1, 1024>>>(SIi, Sm, 128);
    GEMM(T3, 128, E11, 128, 0, E + 128, 256, 0, 128, 128, 128, 1.f, 0.f, 0);
    GEMM(EI + 128 * 256, 256, SIi, 128, 0, T2, 128, 0, 128, 128, 128, -1.f, 0.f, 0);
    GEMM(EI + 128, 256, T3, 128, 0, SIi, 128, 0, 128, 128, 128, -1.f, 0.f, 0);
    k_axcopy<<<64, 256>>>(EI, 256, E11, 128, 128, 128, 1.f, 0.f);
    GEMM(EI, 256, T3, 128, 0, EI + 128 * 256, 256, 0, 128, 128, 128, -1.f, 1.f, 0);
    k_axcopy<<<64, 256>>>(EI + 128 * 256 + 128, 256, SIi, 128, 128, 128, 1.f, 0.f);
    // weights W = inv(E) [Fm | B1 | B2]
    GEMM(WFM, 256, EI, 256, 0, H + 512 * 768, 768, 0, 256, 256, 256, 1.f, 0.f, 0);
    GEMM(WB1, 256, EI, 256, 0, H + 512 * 768 + 256, 768, 0, 256, 256, 256, 1.f, 0.f, 0);
    GEMM(WB2, 128, EI, 256, 0, B2, 128, 0, 256, 128, 256, 1.f, 0.f, 0);
    k_cvtW2<<<960, 256>>>(WH2, WL2, WFM, WB1, WB2, C2, D21, MT);

    // batch: CXW = [xi|w] @ [C1|D12]^T   (tensor cores, split-bf16)
    {
        dim3 g1(2, BB / 128);
        mmagemm<<<g1, 256>>>(xi, 256, w, 128, nullptr, 0,
                             WH1, WL1, 384, 256, 256, CXW, 256, nullptr, 0);
    }
    recur<<<BB / 64, 256>>>(CXW, EPS, DNT, IL);
    // batch: {xn,u} = [xi|eps|w] @ [WFM|WB1|WB2 ; C2|D21|gMt]^T
    {
        dim3 g2(3, BB / 128);
        mmagemm<<<g2, 256>>>(xi, 256, EPS, 256, w, 128,
                             WH2, WL2, 640, 384, 256, xn, 256, u, 128);
    }
}

// round 15
// speedup vs baseline: 1.0993x; 1.0993x over previous
#include <cuda_runtime.h>
#include <cuda_bf16.h>
#include <cstdint>
#include <cstddef>

#define EPSR 0.001f
#define BB 32768
#define GN 128u

__device__ float g_gam[2];
__device__ unsigned g_barcnt;   // zero-initialized at load; monotonic phases

constexpr size_t F128 = 128*128;
constexpr size_t OFF_H   = 0;
constexpr size_t OFF_EPS = OFF_H + 768*768;
constexpr size_t OFF_CXW = OFF_EPS + (size_t)BB*256;
constexpr size_t OFF_MT  = OFF_CXW + (size_t)BB*256;
constexpr size_t OFF_AP  = OFF_MT  + F128;
constexpr size_t OFF_AM  = OFF_AP  + F128;
constexpr size_t OFF_AI  = OFF_AM  + F128;
constexpr size_t OFF_G   = OFF_AI  + F128;
constexpr size_t OFF_GI  = OFF_G   + F128;
constexpr size_t OFF_MM  = OFF_GI  + F128;
constexpr size_t OFF_E11 = OFF_MM  + F128;
constexpr size_t OFF_S   = OFF_E11 + F128;
constexpr size_t OFF_SI  = OFF_S   + F128;
constexpr size_t OFF_T2  = OFF_SI  + F128;
constexpr size_t OFF_T3  = OFF_T2  + F128;
constexpr size_t OFF_VR  = OFF_T3  + F128;
constexpr size_t OFF_T1  = OFF_VR  + 768*128;
constexpr size_t OFF_E   = OFF_T1  + 768*128;
constexpr size_t OFF_EI  = OFF_E   + 256*256;
constexpr size_t OFF_WFM = OFF_EI  + 256*256;
constexpr size_t OFF_WB1 = OFF_WFM + 256*256;
constexpr size_t OFF_DNT = OFF_WB1 + 256*256;
constexpr size_t OFF_WB2 = OFF_DNT + 256*256;
constexpr size_t OFF_IL  = OFF_WB2 + 256*128;
constexpr size_t SCR_TOT = OFF_IL  + 256;

__device__ float g_scr[SCR_TOT];

__device__ __nv_bfloat16 g_wh1[256*384];
__device__ __nv_bfloat16 g_wl1[256*384];
__device__ __nv_bfloat16 g_wh2[384*640];
__device__ __nv_bfloat16 g_wl2[384*640];

// ---------- packed fp32x2 helpers ----------
__device__ __forceinline__ unsigned long long pk2(float x, float y) {
    unsigned long long r;
    asm("mov.b64 %0, {%1,%2};" : "=l"(r) : "f"(x), "f"(y));
    return r;
}
__device__ __forceinline__ void upk2(unsigned long long v, float &x, float &y) {
    asm("mov.b64 {%0,%1}, %2;" : "=f"(x), "=f"(y) : "l"(v));
}
__device__ __forceinline__ void ffma2(unsigned long long &d, unsigned long long a,
                                      unsigned long long b) {
    asm("fma.rn.f32x2 %0, %1, %2, %0;" : "+l"(d) : "l"(a), "l"(b));
}

// ---------- software grid barrier (all 128 CTAs resident) ----------
__device__ __forceinline__ void gbar() {
    __syncthreads();
    if (threadIdx.x == 0) {
        __threadfence();
        unsigned old = atomicAdd(&g_barcnt, 1u);
        unsigned target = (old / GN + 1u) * GN;
        unsigned cur;
        do {
            asm volatile("ld.volatile.global.u32 %0, [%1];" : "=r"(cur) : "l"(&g_barcnt));
        } while (cur < target);
        __threadfence();
    }
    __syncthreads();
}

// ---------- device GEMM: 64x64 tiles distributed across the grid ----------
struct SmemT { float sA[16][68]; float sB[16][68]; };

__device__ void dgemm(SmemT& sm, float* C, int ldc,
                      const float* A, int lda, int tA,
                      const float* B, int ldb, int tB,
                      int M, int N, int K,
                      float alpha, int amode,
                      float beta, const float* Csrc, int ldsrc,
                      float diag)
{
    int tid = threadIdx.x;
    int ntn = N >> 6;
    int tiles = (M >> 6) * ntn;
    float al = alpha;
    if (amode == 2) al *= g_gam[1];
    int ty = tid >> 4, tx = tid & 15;
    for (int tIdx = blockIdx.x; tIdx < tiles; tIdx += (int)GN) {
        int bi = tIdx / ntn;
        int bm = bi << 6, bn = (tIdx - bi * ntn) << 6;
        unsigned long long acc[4][2];
#pragma unroll
        for (int r = 0; r < 4; r++) { acc[r][0] = 0ull; acc[r][1] = 0ull; }
        for (int k0 = 0; k0 < K; k0 += 16) {
            __syncthreads();
            if (!tA) {
                int r = tid >> 2, c4 = (tid & 3) << 2;
                float4 v = *(const float4*)(A + (size_t)(bm + r) * lda + k0 + c4);
                sm.sA[c4][r] = v.x; sm.sA[c4 + 1][r] = v.y;
                sm.sA[c4 + 2][r] = v.z; sm.sA[c4 + 3][r] = v.w;
            } else {
                int kk = tid >> 4, m4 = (tid & 15) << 2;
                *(float4*)&sm.sA[kk][m4] =
                    *(const float4*)(A + (size_t)(k0 + kk) * lda + bm + m4);
            }
            if (!tB) {
                int kk = tid >> 4, n4 = (tid & 15) << 2;
                *(float4*)&sm.sB[kk][n4] =
                    *(const float4*)(B + (size_t)(k0 + kk) * ldb + bn + n4);
            } else {
                int n = tid >> 2, c4 = (tid & 3) << 2;
                float4 v = *(const float4*)(B + (size_t)(bn + n) * ldb + k0 + c4);
                sm.sB[c4][n] = v.x; sm.sB[c4 + 1][n] = v.y;
                sm.sB[c4 + 2][n] = v.z; sm.sB[c4 + 3][n] = v.w;
            }
            __syncthreads();
#pragma unroll
            for (int kk = 0; kk < 16; kk++) {
                float4 av = *(float4*)&sm.sA[kk][ty << 2];
                float4 bv = *(float4*)&sm.sB[kk][tx << 2];
                unsigned long long bp0 = pk2(bv.x, bv.y), bp1 = pk2(bv.z, bv.w);
                float ar[4] = {av.x, av.y, av.z, av.w};
#pragma unroll
                for (int r = 0; r < 4; r++) {
                    unsigned long long ap = pk2(ar[r], ar[r]);
                    ffma2(acc[r][0], ap, bp0);
                    ffma2(acc[r][1], ap, bp1);
                }
            }
        }
#pragma unroll
        for (int r = 0; r < 4; r++) {
            int m = bm + (ty << 2) + r;
            float o[4];
            upk2(acc[r][0], o[0], o[1]);
            upk2(acc[r][1], o[2], o[3]);
            float* crow = C + (size_t)m * ldc + bn + (tx << 2);
            const float* srow = Csrc ? (Csrc + (size_t)m * ldsrc + bn + (tx << 2)) : nullptr;
#pragma unroll
            for (int c = 0; c < 4; c++) {
                float x = al * o[c];
                if (srow) x += beta * srow[c];
                int n = bn + (tx << 2) + c;
                if (diag != 0.f && m == n) x += diag;
                crow[c] = x;
            }
        }
    }
}

// ---------- phase A segment kernels ----------
#define GT (int)(GN * 256)
#define S0P g_scr

__global__ __launch_bounds__(256) void seg1(const float* __restrict__ X3,
                                            const float* __restrict__ Y3,
                                            const float* __restrict__ sg) {
    __shared__ SmemT sm;
    int gtid = blockIdx.x * 256 + threadIdx.x;
    if (gtid == 0) {
        float g = sg[0] * sg[0];
        g_gam[0] = g; g_gam[1] = 1.f / g;
    }
    float *MM = S0P + OFF_MM, *AP = S0P + OFF_AP, *AM = S0P + OFF_AM;
    dgemm(sm, MM, 128, X3, 128, 0, X3, 128, 1, 128, 128, 128, 1.f, 0, 0.f, nullptr, 0, 0.f);
    gbar();
    for (int t = gtid; t < 128 * 128; t += GT) {
        int i = t >> 7, j = t & 127;
        float v = MM[t] + Y3[t] - Y3[j * 128 + i] + ((i == j) ? EPSR : 0.f);
        float d = (i == j) ? 1.f : 0.f;
        AP[t] = d + v; AM[t] = d - v;
    }
}

__global__ __launch_bounds__(256) void seg2() {
    __shared__ SmemT sm;
    float *MT = S0P + OFF_MT, *AM = S0P + OFF_AM, *AI = S0P + OFF_AI, *G = S0P + OFF_G;
    dgemm(sm, MT, 128, AM, 128, 0, AI, 128, 0, 128, 128, 128, 1.f, 0, 0.f, nullptr, 0, 0.f);
    gbar();
    dgemm(sm, G, 128, MT, 128, 1, MT, 128, 0, 128, 128, 128, -1.f, 0, 0.f, nullptr, 0, 1.f);
}

__global__ __launch_bounds__(256) void seg3(const float* __restrict__ X,
                                            const float* __restrict__ Y,
                                            const float* __restrict__ B2,
                                            const float* __restrict__ C2,
                                            const float* __restrict__ D21,
                                            const float* __restrict__ D12) {
    __shared__ SmemT sm;
    int gtid = blockIdx.x * 256 + threadIdx.x;
    float *H = S0P + OFF_H, *MT = S0P + OFF_MT, *GI = S0P + OFF_GI,
          *VR = S0P + OFF_VR, *T1 = S0P + OFF_T1, *E = S0P + OFF_E,
          *DNT = S0P + OFF_DNT, *IL = S0P + OFF_IL;
    // vec_R and H = X^T X + eps I (independent)
    dgemm(sm, VR, 128, C2, 256, 1, MT, 128, 0, 256, 128, 128, -1.f, 0, 0.f, nullptr, 0, 0.f);
    dgemm(sm, VR + 256 * 128, 128, D21, 256, 1, MT, 128, 0, 256, 128, 128,
          -1.f, 0, -1.f, D12, 128, 0.f);
    for (int t = gtid; t < 256 * 128; t += GT) VR[512 * 128 + t] = B2[t];
    dgemm(sm, H, 768, X, 768, 1, X, 768, 0, 768, 768, 768, 1.f, 0, 0.f, nullptr, 0, EPSR);
    gbar();
    dgemm(sm, T1, 128, VR, 128, 0, GI, 128, 0, 768, 128, 128, 1.f, 0, 0.f, nullptr, 0, 0.f);
    gbar();
    dgemm(sm, H, 768, T1, 128, 0, VR, 128, 1, 768, 768, 128, 1.f, 2, 1.f, H, 768, 0.f);
    gbar();
    dgemm(sm, H, 768, C2, 256, 1, C2, 256, 0, 256, 256, 128, 1.f, 2, 1.f, H, 768, 0.f);
    dgemm(sm, H + 256, 768, C2, 256, 1, D21, 256, 0, 256, 256, 128, 1.f, 2, 1.f, H + 256, 768, 0.f);
    dgemm(sm, H + 256 * 768, 768, D21, 256, 1, C2, 256, 0, 256, 256, 128,
          1.f, 2, 1.f, H + 256 * 768, 768, 0.f);
    dgemm(sm, H + 256 * 768 + 256, 768, D21, 256, 1, D21, 256, 0, 256, 256, 128,
          1.f, 2, 1.f, H + 256 * 768 + 256, 768, 0.f);
    gbar();
    for (int t = gtid; t < 256 * 256; t += GT) {
        int i = t >> 8, j = t & 255;
        E[t] = 0.5f * (H[(size_t)i * 768 + j] + H[(size_t)(512 + i) * 768 + 512 + j]
                       + Y[t] - Y[(size_t)j * 256 + i]);
    }
    const float* hh = H + 256 * 768 + 256;
    for (int t = gtid; t < 256 * 256; t += GT) {
        int i = t >> 8, j = t & 255;
        DNT[t] = (j > i) ? -hh[(size_t)j * 768 + i] : 0.f;
        if (t < 256) IL[t] = 1.f / hh[(size_t)t * 768 + t];
    }
    for (int t = gtid; t < 256 * 384; t += GT) {
        int n = t / 384, k = t - n * 384;
        float v = (k < 256) ? -H[(size_t)(256 + n) * 768 + k] : D12[n * 128 + (k - 256)];
        __nv_bfloat16 h = __float2bfloat16(v);
        g_wh1[t] = h;
        g_wl1[t] = __float2bfloat16(v - __bfloat162float(h));
    }
}

__global__ __launch_bounds__(256) void seg4() {
    __shared__ SmemT sm;
    float *E = S0P + OFF_E, *E11 = S0P + OFF_E11, *T2 = S0P + OFF_T2,
          *T3 = S0P + OFF_T3, *Sm = S0P + OFF_S;
    dgemm(sm, T2, 128, E + 128 * 256, 256, 0, E11, 128, 0, 128, 128, 128,
          1.f, 0, 0.f, nullptr, 0, 0.f);
    dgemm(sm, T3, 128, E11, 128, 0, E + 128, 256, 0, 128, 128, 128,
          1.f, 0, 0.f, nullptr, 0, 0.f);
    gbar();
    dgemm(sm, Sm, 128, T2, 128, 0, E + 128, 256, 0, 128, 128, 128,
          -1.f, 0, 1.f, E + 128 * 256 + 128, 256, 0.f);
}

__global__ __launch_bounds__(256) void seg5(const float* __restrict__ B2,
                                            const float* __restrict__ C2,
                                            const float* __restrict__ D21) {
    __shared__ SmemT sm;
    int gtid = blockIdx.x * 256 + threadIdx.x;
    float *H = S0P + OFF_H, *E11 = S0P + OFF_E11, *SIi = S0P + OFF_SI,
          *T2 = S0P + OFF_T2, *T3 = S0P + OFF_T3, *EI = S0P + OFF_EI,
          *WFM = S0P + OFF_WFM, *WB1 = S0P + OFF_WB1, *WB2 = S0P + OFF_WB2,
          *MT = S0P + OFF_MT;
    dgemm(sm, EI + 128 * 256, 256, SIi, 128, 0, T2, 128, 0, 128, 128, 128,
          -1.f, 0, 0.f, nullptr, 0, 0.f);
    dgemm(sm, EI + 128, 256, T3, 128, 0, SIi, 128, 0, 128, 128, 128,
          -1.f, 0, 0.f, nullptr, 0, 0.f);
    for (int t = gtid; t < 128 * 128; t += GT) {
        int i = t >> 7, j = t & 127;
        EI[(size_t)(128 + i) * 256 + 128 + j] = SIi[t];
    }
    gbar();
    dgemm(sm, EI, 256, T3, 128, 0, EI + 128 * 256, 256, 0, 128, 128, 128,
          -1.f, 0, 1.f, E11, 128, 0.f);
    gbar();
    dgemm(sm, WFM, 256, EI, 256, 0, H + 512 * 768, 768, 0, 256, 256, 256,
          1.f, 0, 0.f, nullptr, 0, 0.f);
    dgemm(sm, WB1, 256, EI, 256, 0, H + 512 * 768 + 256, 768, 0, 256, 256, 256,
          1.f, 0, 0.f, nullptr, 0, 0.f);
    dgemm(sm, WB2, 128, EI, 256, 0, B2, 128, 0, 256, 128, 256,
          1.f, 0, 0.f, nullptr, 0, 0.f);
    gbar();
    for (int t = gtid; t < 384 * 640; t += GT) {
        int n = t / 640, k = t - n * 640;
        float v;
        if (n < 256) {
            v = (k < 256) ? WFM[n * 256 + k]
              : (k < 512) ? WB1[n * 256 + (k - 256)]
                          : WB2[n * 128 + (k - 512)];
        } else {
            int m = n - 256;
            v = (k < 256) ? C2[m * 256 + k]
              : (k < 512) ? D21[m * 256 + (k - 256)]
                          : g_gam[0] * MT[m * 128 + (k - 512)];
        }
        __nv_bfloat16 h = __float2bfloat16(v);
        g_wh2[t] = h;
        g_wl2[t] = __float2bfloat16(v - __bfloat162float(h));
    }
}

// ---------- lean Gauss-Jordan inverse, n=128 (uniform rank-1 sweep) ----------
__global__ __launch_bounds__(1024) void gj(float* dst, const float* src, int ld) {
    __shared__ float colb[2][128];
    __shared__ float rowr[2][128];
    __shared__ float ivs[2];
    int t = threadIdx.x, j = t & 127, q = t >> 7, base = q << 4;
    float v[16];
#pragma unroll
    for (int i = 0; i < 16; i++) v[i] = src[(size_t)(base + i) * ld + j];
    if (j == 0) {
#pragma unroll
        for (int i = 0; i < 16; i++) colb[0][base + i] = (base + i == 0) ? v[i] - 1.f : v[i];
    }
    if (q == 0) rowr[0][j] = v[0];
    if (t == 0) ivs[0] = 1.f / v[0];
    __syncthreads();
    for (int k = 0; k < 128; k++) {
        int pb = k & 1, nb = pb ^ 1;
        float iv = ivs[pb];
        float a = (j == k) ? (1.f + iv) : rowr[pb][j] * iv;
#pragma unroll
        for (int i = 0; i < 16; i++) v[i] -= colb[pb][base + i] * a;
        int kn = k + 1;
        if (kn < 128) {
            if (j == kn) {
#pragma unroll
                for (int i = 0; i < 16; i++)
                    colb[nb][base + i] = (base + i == kn) ? v[i] - 1.f : v[i];
            }
            if (q == (kn >> 4)) {
                float pv = v[kn & 15];
                rowr[nb][j] = pv;
                if (j == kn) ivs[nb] = 1.f / pv;
            }
        }
        __syncthreads();
    }
#pragma unroll
    for (int i = 0; i < 16; i++) dst[(size_t)(base + i) * 128 + j] = v[i];
}

// ---------- tcgen helpers for mmagemm ----------
__device__ __forceinline__ uint32_t s2u(const void* p) {
    uint32_t a;
    asm("{ .reg .u64 t; cvta.to.shared.u64 t, %1; cvt.u32.u64 %0, t; }"
        : "=r"(a) : "l"(p));
    return a;
}
__device__ __forceinline__ void ldm4(uint32_t* r, uint32_t addr) {
    asm volatile("ldmatrix.sync.aligned.m8n8.x4.shared.b16 {%0,%1,%2,%3}, [%4];"
        : "=r"(r[0]), "=r"(r[1]), "=r"(r[2]), "=r"(r[3]) : "r"(addr));
}
#define MMA16816(d, a, b) \
    asm volatile("mma.sync.aligned.m16n8k16.row.col.f32.bf16.bf16.f32 " \
        "{%0,%1,%2,%3}, {%4,%5,%6,%7}, {%8,%9}, {%0,%1,%2,%3};" \
        : "+f"((d)[0]), "+f"((d)[1]), "+f"((d)[2]), "+f"((d)[3]) \
        : "r"((a)[0]), "r"((a)[1]), "r"((a)[2]), "r"((a)[3]), \
          "r"((b)[0]), "r"((b)[1]))

// ---------- tensor-core batch GEMM with split-bf16 (3 products) ----------
__global__ __launch_bounds__(256) void mmagemm(
    const float* __restrict__ A0, int k0,
    const float* __restrict__ A1, int k1,
    const float* __restrict__ A2, int k2,
    const __nv_bfloat16* __restrict__ Wh, const __nv_bfloat16* __restrict__ Wl,
    int ktot, int Ntot, int n0,
    float* __restrict__ C0, int ldc0, float* __restrict__ C1, int ldc1)
{
    __shared__ __nv_bfloat16 sAh[128][40];
    __shared__ __nv_bfloat16 sAl[128][40];
    __shared__ __nv_bfloat16 sWh[128][40];
    __shared__ __nv_bfloat16 sWl[128][40];

    int tid = threadIdx.x;
    int bm = blockIdx.y << 7, bn = blockIdx.x << 7;
    int wi = tid >> 5, lane = tid & 31;
    int wm = (wi & 3) << 5;
    int wn = (wi >> 2) << 6;

    float acc[2][8][4];
#pragma unroll
    for (int mf = 0; mf < 2; mf++)
#pragma unroll
        for (int nf = 0; nf < 8; nf++)
#pragma unroll
            for (int i = 0; i < 4; i++) acc[mf][nf][i] = 0.f;

    int am = tid >> 1, ah = tid & 1;
    float4 pa[4];
    uint4 pwh[2], pwl[2];

    auto ldA = [&](int off) {
        const float* As; int so, sk;
        if (off < k0)           { As = A0; so = off;           sk = k0; }
        else if (off < k0 + k1) { As = A1; so = off - k0;      sk = k1; }
        else                    { As = A2; so = off - k0 - k1; sk = k2; }
        const float4* p = (const float4*)(As + (size_t)(bm + am) * sk + so + ah * 16);
        pa[0] = p[0]; pa[1] = p[1]; pa[2] = p[2]; pa[3] = p[3];
    };
    auto ldW = [&](int off) {
        const uint4* ph = (const uint4*)(Wh + (size_t)(bn + am) * ktot + off + ah * 16);
        pwh[0] = ph[0]; pwh[1] = ph[1];
        const uint4* pl = (const uint4*)(Wl + (size_t)(bn + am) * ktot + off + ah * 16);
        pwl[0] = pl[0]; pwl[1] = pl[1];
    };
    auto stAW = [&]() {
        const float* pf = (const float*)pa;
        uint32_t hh[8], ll[8];
#pragma unroll
        for (int i = 0; i < 8; i++) {
            float x = pf[2 * i], y = pf[2 * i + 1];
            __nv_bfloat162 hb = __float22bfloat162_rn(make_float2(x, y));
            float2 hf = __bfloat1622float2(hb);
            __nv_bfloat162 lb = __float22bfloat162_rn(make_float2(x - hf.x, y - hf.y));
            hh[i] = *(uint32_t*)&hb; ll[i] = *(uint32_t*)&lb;
        }
        int co = ah << 4;
        *(uint4*)&sAh[am][co]     = make_uint4(hh[0], hh[1], hh[2], hh[3]);
        *(uint4*)&sAh[am][co + 8] = make_uint4(hh[4], hh[5], hh[6], hh[7]);
        *(uint4*)&sAl[am][co]     = make_uint4(ll[0], ll[1], ll[2], ll[3]);
        *(uint4*)&sAl[am][co + 8] = make_uint4(ll[4], ll[5], ll[6], ll[7]);
        *(uint4*)&sWh[am][co]     = pwh[0];
        *(uint4*)&sWh[am][co + 8] = pwh[1];
        *(uint4*)&sWl[am][co]     = pwl[0];
        *(uint4*)&sWl[am][co + 8] = pwl[1];
    };

    ldA(0); ldW(0); stAW();
    __syncthreads();

    int ar = lane & 15, akq = (lane >> 4) << 3;
    int brn = lane & 7, bgrp = lane >> 3;
    int bro = (bgrp >> 1) << 3, bko = (bgrp & 1) << 3;

    int nch = ktot >> 5;
    for (int c = 0; c < nch; c++) {
        bool more = (c + 1) < nch;
        if (more) { ldA((c + 1) << 5); ldW((c + 1) << 5); }
#pragma unroll
        for (int ks = 0; ks < 2; ks++) {
            int kc = ks << 4;
            uint32_t ahf[2][4], alf[2][4], bf[8][2];
            ldm4(ahf[0], s2u(&sAh[wm + ar][kc + akq]));
            ldm4(ahf[1], s2u(&sAh[wm + 16 + ar][kc + akq]));
#pragma unroll
            for (int q = 0; q < 4; q++) {
                uint32_t r4[4];
                ldm4(r4, s2u(&sWh[wn + (q << 4) + bro + brn][kc + bko]));
                bf[2 * q][0] = r4[0]; bf[2 * q][1] = r4[1];
                bf[2 * q + 1][0] = r4[2]; bf[2 * q + 1][1] = r4[3];
            }
#pragma unroll
            for (int mf = 0; mf < 2; mf++)
#pragma unroll
                for (int nf = 0; nf < 8; nf++)
                    MMA16816(acc[mf][nf], ahf[mf], bf[nf]);
            ldm4(alf[0], s2u(&sAl[wm + ar][kc + akq]));
            ldm4(alf[1], s2u(&sAl[wm + 16 + ar][kc + akq]));
#pragma unroll
            for (int mf = 0; mf < 2; mf++)
#pragma unroll
                for (int nf = 0; nf < 8; nf++)
                    MMA16816(acc[mf][nf], alf[mf], bf[nf]);
#pragma unroll
            for (int q = 0; q < 4; q++) {
                uint32_t r4[4];
                ldm4(r4, s2u(&sWl[wn + (q << 4) + bro + brn][kc + bko]));
                bf[2 * q][0] = r4[0]; bf[2 * q][1] = r4[1];
                bf[2 * q + 1][0] = r4[2]; bf[2 * q + 1][1] = r4[3];
            }
#pragma unroll
            for (int mf = 0; mf < 2; mf++)
#pragma unroll
                for (int nf = 0; nf < 8; nf++)
                    MMA16816(acc[mf][nf], ahf[mf], bf[nf]);
        }
        __syncthreads();
        if (more) { stAW(); __syncthreads(); }
    }

    int tm = lane >> 2, tn = (lane & 3) << 1;
#pragma unroll
    for (int mf = 0; mf < 2; mf++)
#pragma unroll
        for (int nf = 0; nf < 8; nf++) {
            int m = bm + wm + (mf << 4) + tm;
            int n = bn + wn + (nf << 3) + tn;
            float* d0; float* d1;
            if (n < n0) {
                d0 = C0 + (size_t)m * ldc0 + n;
                d1 = C0 + (size_t)(m + 8) * ldc0 + n;
            } else {
                d0 = C1 + (size_t)m * ldc1 + (n - n0);
                d1 = C1 + (size_t)(m + 8) * ldc1 + (n - n0);
            }
            *(float2*)d0 = make_float2(acc[mf][nf][0], acc[mf][nf][1]);
            *(float2*)d1 = make_float2(acc[mf][nf][2], acc[mf][nf][3]);
        }
}

// ---------- register-resident tanh recurrence ----------
__global__ __launch_bounds__(256) void recur(const float* __restrict__ cxw,
                                             float* __restrict__ eps,
                                             const float* __restrict__ DnT,
                                             const float* __restrict__ IL) {
    __shared__ float sd[2][256];
    __shared__ float se[64];
    __shared__ float sil[256];
    int tid = threadIdx.x;
    int r = tid >> 3, ln = tid & 7;
    int b0 = blockIdx.x << 6;
    size_t row0 = (size_t)(b0 + r) * 256;
    size_t row1 = (size_t)(b0 + r + 32) * 256;

    float a0[32], a1[32];
#pragma unroll
    for (int c = 0; c < 32; c++) {
        a0[c] = cxw[row0 + (c << 3) + ln];
        a1[c] = cxw[row1 + (c << 3) + ln];
    }
    sil[tid] = IL[tid];
    sd[0][tid] = DnT[tid];
    float nv0 = a0[0], nv1 = a1[0];
    float eo0 = 0.f, eo1 = 0.f;
    __syncthreads();

    for (int i = 0; i < 256; i++) {
        if (ln == (i & 7)) {
            float il = sil[i];
            eo0 = tanhf(nv0 * il);
            eo1 = tanhf(nv1 * il);
            se[r] = eo0; se[r + 32] = eo1;
        }
        __syncthreads();
        float e0 = se[r], e1 = se[r + 32];
        const float* d = sd[i & 1];
        if (i < 255) sd[(i + 1) & 1][tid] = DnT[((i + 1) << 8) + tid];
#pragma unroll
        for (int c = 0; c < 32; c++) {
            int dji = ((c << 3) + ln) - i;
            float dv = d[(c << 3) + ln];
            if (dji > 0) {
                a0[c] = fmaf(e0, dv, a0[c]);
                a1[c] = fmaf(e1, dv, a1[c]);
            }
            if (dji == 0) { a0[c] = eo0; a1[c] = eo1; }
            if (dji == 1) { nv0 = a0[c]; nv1 = a1[c]; }
        }
        __syncthreads();
    }
#pragma unroll
    for (int c = 0; c < 32; c++) {
        eps[row0 + (c << 3) + ln] = a0[c];
        eps[row1 + (c << 3) + ln] = a1[c];
    }
}

extern "C" void kernel_launch(void* const* d_in, const int* in_sizes, int n_in,
                              void* d_out, int out_size) {
    const float* w   = (const float*)d_in[0];
    const float* xi  = (const float*)d_in[1];
    const float* X   = (const float*)d_in[2];
    const float* Y   = (const float*)d_in[3];
    const float* B2  = (const float*)d_in[4];
    const float* C2  = (const float*)d_in[5];
    const float* D21 = (const float*)d_in[6];
    const float* X3  = (const float*)d_in[7];
    const float* Y3  = (const float*)d_in[8];
    const float* sg  = (const float*)d_in[9];
    const float* D12 = (const float*)d_in[10];

    float* S0 = nullptr;
    cudaGetSymbolAddress((void**)&S0, g_scr);
    __nv_bfloat16 *WH1, *WL1, *WH2, *WL2;
    cudaGetSymbolAddress((void**)&WH1, g_wh1);
    cudaGetSymbolAddress((void**)&WL1, g_wl1);
    cudaGetSymbolAddress((void**)&WH2, g_wh2);
    cudaGetSymbolAddress((void**)&WL2, g_wl2);

    float *EPS = S0 + OFF_EPS, *CXW = S0 + OFF_CXW,
          *AP = S0 + OFF_AP, *AI = S0 + OFF_AI, *G = S0 + OFF_G,
          *GI = S0 + OFF_GI, *E11 = S0 + OFF_E11, *Sm = S0 + OFF_S,
          *SIi = S0 + OFF_SI, *E = S0 + OFF_E,
          *DNT = S0 + OFF_DNT, *IL = S0 + OFF_IL;

    float* u  = (float*)d_out;
    float* xn = (float*)d_out + (size_t)BB * 128;

    seg1<<<GN, 256>>>(X3, Y3, sg);
    gj<<<1, 1024>>>(AI, AP, 128);
    seg2<<<GN, 256>>>();
    gj<<<1, 1024>>>(GI, G, 128);
    seg3<<<GN, 256>>>(X, Y, B2, C2, D21, D12);
    gj<<<1, 1024>>>(E11, E, 256);
    seg4<<<GN, 256>>>();
    gj<<<1, 1024>>>(SIi, Sm, 128);
    seg5<<<GN, 256>>>(B2, C2, D21);

    // batch: CXW = [xi|w] @ [C1|D12]^T   (tensor cores, split-bf16)
    {
        dim3 g1(2, BB / 128);
        mmagemm<<<g1, 256>>>(xi, 256, w, 128, nullptr, 0,
                             WH1, WL1, 384, 256, 256, CXW, 256, nullptr, 0);
    }
    recur<<<BB / 64, 256>>>(CXW, EPS, DNT, IL);
    // batch: {xn,u} = [xi|eps|w] @ [WFM|WB1|WB2 ; C2|D21|gMt]^T
    {
        dim3 g2(3, BB / 128);
        mmagemm<<<g2, 256>>>(xi, 256, EPS, 256, w, 128,
                             WH2, WL2, 640, 384, 256, xn, 256, u, 128);
    }
}